// round 1
// baseline (speedup 1.0000x reference)
#include <cuda_runtime.h>

// SSIM loss, 1-D, window 11, sigma 1.5, zero padding 5.
// B=16, C=32, T=48000 -> 512 rows of 48000.
// Strategy: per block, one tile of 2048 outputs of one row.
//   Stage (u, v, u^2, v^2) with u=p+t, v=p-t as interleaved float4 in SMEM
//   (padded layout for conflict-free LDS.128), then each thread computes 8
//   consecutive outputs via a register sliding window: 4 convs x 11 taps,
//   weights as immediates (FFMA-imm, rt 1).
// SSIM reconstruction:
//   a=U^2-V^2, b=U^2+V^2, c=Cu-Cv, d=Cu+Cv
//   num = (a/2 + C1)((c-a)/2 + C2),  den = (b/2 + C1)((d-b)/2 + C2)
//   loss += 1 - num/den  (valid outputs only)
// Block reduce -> fp64 atomicAdd -> finalize kernel divides by N.

#define TT    48000
#define NROWS (16 * 32)
#define TILE  2048
#define TPB   256
#define RPT   8
#define HALO  5
#define NLOAD (TILE + 2 * HALO)       // 2058
#define C1F   (1.0e-4f)               // 0.01^2
#define C2F   (9.0e-4f)               // 0.03^2

__device__ double g_sum;

__global__ void zero_k() { g_sum = 0.0; }

__global__ __launch_bounds__(TPB) void ssim_k(const float* __restrict__ pred,
                                              const float* __restrict__ tgt) {
    // padded interleaved buffer: phys index = i + (i>>3)  (conflict-free for
    // lane stride of 8 float4s: 9*16B = 144B -> banks 4*ln..4*ln+3, all distinct)
    __shared__ float4 sbuf[NLOAD + (NLOAD >> 3) + 2];
    __shared__ float  wsum[TPB / 32];

    const int tile = blockIdx.x;
    const int row  = blockIdx.y;
    const int tid  = threadIdx.x;

    const int rowBase   = row * TT;
    const int tileStart = tile * TILE;

    // ---- load phase: p,t -> (u, v, u^2, v^2) float4, zero pad outside row ----
    for (int i = tid; i < NLOAD; i += TPB) {
        int src = tileStart - HALO + i;
        float p = 0.0f, t = 0.0f;
        if (src >= 0 && src < TT) {
            p = pred[rowBase + src];
            t = tgt[rowBase + src];
        }
        float u = p + t;
        float v = p - t;
        sbuf[i + (i >> 3)] = make_float4(u, v, u * u, v * v);
    }
    __syncthreads();

    // Gaussian(11, sigma=1.5), normalized; symmetric. Compile-time literals so
    // ptxas can emit immediate-form FFMA (rt_SMSP = 1).
    constexpr float W[11] = {
        0.001028380f, 0.007598758f, 0.036000773f, 0.109360755f, 0.213005542f,
        0.266011585f,
        0.213005542f, 0.109360755f, 0.036000773f, 0.007598758f, 0.001028380f
    };

    float U[RPT], V[RPT], Pu[RPT], Pv[RPT];
#pragma unroll
    for (int j = 0; j < RPT; j++) { U[j] = 0.f; V[j] = 0.f; Pu[j] = 0.f; Pv[j] = 0.f; }

    const int s = tid * RPT;   // logical index into sbuf (already includes halo offset)

#pragma unroll
    for (int k = 0; k < RPT + 2 * HALO; k++) {      // 18 sliding loads
        int li = s + k;
        float4 q = sbuf[li + (li >> 3)];
#pragma unroll
        for (int j = 0; j < RPT; j++) {
            int w = k - j;
            if (w >= 0 && w <= 10) {
                U[j]  += q.x * W[w];
                V[j]  += q.y * W[w];
                Pu[j] += q.z * W[w];
                Pv[j] += q.w * W[w];
            }
        }
    }

    // ---- epilogue: SSIM per output, accumulate 1 - ssim ----
    float lsum = 0.0f;
    const int outBase = tileStart + s;
#pragma unroll
    for (int j = 0; j < RPT; j++) {
        float U2 = U[j] * U[j];
        float V2 = V[j] * V[j];
        float a = U2 - V2;
        float b = U2 + V2;
        float c = Pu[j] - Pv[j];
        float d = Pu[j] + Pv[j];
        float num = fmaf(0.5f, a, C1F) * fmaf(0.5f, c, fmaf(-0.5f, a, C2F));
        float den = fmaf(0.5f, b, C1F) * fmaf(0.5f, d, fmaf(-0.5f, b, C2F));
        float ssim = __fdividef(num, den);
        if (outBase + j < TT) lsum += 1.0f - ssim;
    }

    // ---- block reduce ----
#pragma unroll
    for (int off = 16; off; off >>= 1)
        lsum += __shfl_down_sync(0xffffffffu, lsum, off);
    const int wid  = tid >> 5;
    const int lane = tid & 31;
    if (lane == 0) wsum[wid] = lsum;
    __syncthreads();
    if (tid < 32) {
        float v2 = (tid < TPB / 32) ? wsum[tid] : 0.0f;
#pragma unroll
        for (int off = 4; off; off >>= 1)
            v2 += __shfl_down_sync(0xffffffffu, v2, off);
        if (tid == 0) atomicAdd(&g_sum, (double)v2);
    }
}

__global__ void fin_k(float* out) {
    out[0] = (float)(g_sum / (double)((long long)NROWS * TT));
}

extern "C" void kernel_launch(void* const* d_in, const int* in_sizes, int n_in,
                              void* d_out, int out_size) {
    (void)in_sizes; (void)n_in; (void)out_size;
    const float* pred = (const float*)d_in[0];
    const float* tgt  = (const float*)d_in[1];

    zero_k<<<1, 1>>>();
    dim3 grid((TT + TILE - 1) / TILE, NROWS);
    ssim_k<<<grid, TPB>>>(pred, tgt);
    fin_k<<<1, 1>>>((float*)d_out);
}

// round 2
// speedup vs baseline: 1.5715x; 1.5715x over previous
#include <cuda_runtime.h>

// SSIM 1-D loss, window 11, sigma 1.5, zero pad 5. B=16,C=32,T=48000 -> 512 rows.
// Single-kernel design:
//   grid (24, 512): one block per 2048-output tile of one row.
//   Stage u=p+t, v=p-t as packed (u,v) and (u^2,v^2) 64-bit pairs in padded SMEM,
//   conv all 4 channels with fma.rn.f32x2 (2 FMA/instr), 8 outputs/thread.
//   Block partial -> g_part[bid]; last block (atomicInc) reduces + writes d_out.

#define TT     48000
#define NROWS  512
#define TILE   2048
#define TPB    256
#define RPT    8
#define NTILES 24
#define NBLK   (NTILES * NROWS)
#define NL     (TILE + 16)            // logical buffer: [tileStart-8, tileStart+TILE+8)
#define SSZ    (NL + (NL >> 3) + 4)
#define C1F    1.0e-4f
#define C2F    9.0e-4f

__device__ float g_part[NBLK];
__device__ unsigned int g_cnt = 0;    // self-resetting via atomicInc wrap

__device__ __forceinline__ unsigned long long pk2(float lo, float hi) {
    unsigned long long r;
    asm("mov.b64 %0, {%1, %2};" : "=l"(r) : "f"(lo), "f"(hi));
    return r;
}
__device__ __forceinline__ void upk2(unsigned long long v, float& lo, float& hi) {
    asm("mov.b64 {%0, %1}, %2;" : "=f"(lo), "=f"(hi) : "l"(v));
}
__device__ __forceinline__ unsigned long long ffma2(unsigned long long a,
                                                    unsigned long long b,
                                                    unsigned long long c) {
    unsigned long long d;
    asm("fma.rn.f32x2 %0, %1, %2, %3;" : "=l"(d) : "l"(a), "l"(b), "l"(c));
    return d;
}

__global__ __launch_bounds__(TPB) void ssim_k(const float* __restrict__ pred,
                                              const float* __restrict__ tgt,
                                              float* __restrict__ out) {
    __shared__ unsigned long long sUV[SSZ];   // (u, v) packed
    __shared__ unsigned long long sPQ[SSZ];   // (u^2, v^2) packed
    __shared__ float  wsum[TPB / 32];
    __shared__ double dsh[TPB / 32];
    __shared__ int    isLast;

    const int tid       = threadIdx.x;
    const int tile      = blockIdx.x;
    const int row       = blockIdx.y;
    const int rowBase   = row * TT;
    const int tileStart = tile * TILE;

    // ---- interior load: 8 elements per thread, vectorized; TT%8==0 so vectors
    //      are either fully in-row or fully out (zero) ----
    {
        const int src0 = tileStart + tid * RPT;
        float p[RPT], t[RPT];
        if (src0 + RPT - 1 < TT) {
            const float4* pp = reinterpret_cast<const float4*>(pred + rowBase + src0);
            const float4* tp = reinterpret_cast<const float4*>(tgt  + rowBase + src0);
            float4 pa = pp[0], pb = pp[1];
            float4 ta = tp[0], tb = tp[1];
            p[0]=pa.x; p[1]=pa.y; p[2]=pa.z; p[3]=pa.w;
            p[4]=pb.x; p[5]=pb.y; p[6]=pb.z; p[7]=pb.w;
            t[0]=ta.x; t[1]=ta.y; t[2]=ta.z; t[3]=ta.w;
            t[4]=tb.x; t[5]=tb.y; t[6]=tb.z; t[7]=tb.w;
        } else {
#pragma unroll
            for (int e = 0; e < RPT; e++) { p[e] = 0.f; t[e] = 0.f; }
        }
        const int i0  = 8 + tid * RPT;        // multiple of 8 -> (i0+e)>>3 constant
        const int ph0 = i0 + (i0 >> 3);
#pragma unroll
        for (int e = 0; e < RPT; e++) {
            float u = p[e] + t[e];
            float v = p[e] - t[e];
            sUV[ph0 + e] = pk2(u, v);
            sPQ[ph0 + e] = pk2(u * u, v * v);
        }
    }
    // ---- halos (5 each side), zero outside the row ----
    if (tid < 5) {                                   // left: i = 3+tid
        int src = tileStart - 5 + tid;
        float p = 0.f, t = 0.f;
        if (src >= 0) { p = pred[rowBase + src]; t = tgt[rowBase + src]; }
        int i = 3 + tid, ph = i + (i >> 3);
        float u = p + t, v = p - t;
        sUV[ph] = pk2(u, v);
        sPQ[ph] = pk2(u * u, v * v);
    } else if (tid >= 8 && tid < 13) {               // right: i = TILE+8+(tid-8)
        int src = tileStart + TILE + (tid - 8);
        float p = 0.f, t = 0.f;
        if (src < TT) { p = pred[rowBase + src]; t = tgt[rowBase + src]; }
        int i = TILE + 8 + (tid - 8), ph = i + (i >> 3);
        float u = p + t, v = p - t;
        sUV[ph] = pk2(u, v);
        sPQ[ph] = pk2(u * u, v * v);
    }
    __syncthreads();

    // ---- packed Gaussian weights ----
    const float Wv[11] = {
        0.001028380f, 0.007598758f, 0.036000773f, 0.109360755f, 0.213005542f,
        0.266011585f,
        0.213005542f, 0.109360755f, 0.036000773f, 0.007598758f, 0.001028380f
    };
    unsigned long long wp[11];
#pragma unroll
    for (int w = 0; w < 11; w++) wp[w] = pk2(Wv[w], Wv[w]);

    // ---- sliding-window conv, 4 channels as 2 packed accumulator sets ----
    unsigned long long aUV[RPT], aPQ[RPT];
#pragma unroll
    for (int j = 0; j < RPT; j++) { aUV[j] = 0ull; aPQ[j] = 0ull; }

    const int s = tid * RPT + 3;                     // first read index (logical)
#pragma unroll
    for (int k = 0; k < RPT + 10; k++) {             // 18 packed loads
        int li = s + k;
        int ph = li + (li >> 3);
        unsigned long long quv = sUV[ph];
        unsigned long long qpq = sPQ[ph];
#pragma unroll
        for (int j = 0; j < RPT; j++) {
            int w = k - j;
            if (w >= 0 && w < 11) {
                aUV[j] = ffma2(quv, wp[w], aUV[j]);
                aPQ[j] = ffma2(qpq, wp[w], aPQ[j]);
            }
        }
    }

    // ---- epilogue: SSIM per output ----
    float lsum = 0.0f;
    const int o0 = tileStart + tid * RPT;
#pragma unroll
    for (int j = 0; j < RPT; j++) {
        float U, V, Pu, Pv;
        upk2(aUV[j], U, V);
        upk2(aPQ[j], Pu, Pv);
        float U2 = U * U;
        float V2 = V * V;
        float t1 = fmaf(0.5f, U2, C1F);
        float a2 = fmaf(-0.5f, V2, t1);              // (U2-V2)/2 + C1
        float b2 = fmaf( 0.5f, V2, t1);              // (U2+V2)/2 + C1
        float t2 = fmaf(0.5f, Pu, C2F);
        float t3 = fmaf(-0.5f, U2, t2);
        float c2 = fmaf(-0.5f, Pv, fmaf( 0.5f, V2, t3));  // (Cu-Cv)/2-(U2-V2)/2+C2
        float d2 = fmaf( 0.5f, Pv, fmaf(-0.5f, V2, t3));  // (Cu+Cv)/2-(U2+V2)/2+C2
        float num  = a2 * c2;
        float den  = b2 * d2;
        float ssim = __fdividef(num, den);
        if (o0 + j < TT) lsum += 1.0f - ssim;
    }

    // ---- block reduce ----
#pragma unroll
    for (int off = 16; off; off >>= 1)
        lsum += __shfl_down_sync(0xffffffffu, lsum, off);
    const int wid  = tid >> 5;
    const int lane = tid & 31;
    if (lane == 0) wsum[wid] = lsum;
    __syncthreads();

    const int bid = blockIdx.y * gridDim.x + blockIdx.x;
    if (tid < 32) {
        float v2 = (tid < TPB / 32) ? wsum[tid] : 0.0f;
#pragma unroll
        for (int off = 4; off; off >>= 1)
            v2 += __shfl_down_sync(0xffffffffu, v2, off);
        if (tid == 0) {
            g_part[bid] = v2;
            __threadfence();
            unsigned int old = atomicInc(&g_cnt, NBLK - 1u);
            isLast = (old == NBLK - 1u) ? 1 : 0;
        }
    }
    __syncthreads();

    // ---- last block reduces all partials and writes the scalar ----
    if (isLast) {
        double ds = 0.0;
        for (int k = tid; k < NBLK; k += TPB)
            ds += (double)g_part[k];
#pragma unroll
        for (int off = 16; off; off >>= 1)
            ds += __shfl_down_sync(0xffffffffu, ds, off);
        if (lane == 0) dsh[wid] = ds;
        __syncthreads();
        if (tid == 0) {
            double tot = 0.0;
#pragma unroll
            for (int i = 0; i < TPB / 32; i++) tot += dsh[i];
            out[0] = (float)(tot / (double)((long long)NROWS * TT));
        }
    }
}

extern "C" void kernel_launch(void* const* d_in, const int* in_sizes, int n_in,
                              void* d_out, int out_size) {
    (void)in_sizes; (void)n_in; (void)out_size;
    const float* pred = (const float*)d_in[0];
    const float* tgt  = (const float*)d_in[1];
    dim3 grid(NTILES, NROWS);
    ssim_k<<<grid, TPB>>>(pred, tgt, (float*)d_out);
}